// round 2
// baseline (speedup 1.0000x reference)
#include <cuda_runtime.h>
#include <math.h>
#include <stdint.h>

#define FULL 0xFFFFFFFFu
#define WARPS_PER_BLOCK 8

__global__ __launch_bounds__(WARPS_PER_BLOCK * 32)
void topk_route_kernel(const float* __restrict__ logits,
                       const float* __restrict__ bias,
                       float* __restrict__ out,
                       int T)
{
    __shared__ float s_scores[WARPS_PER_BLOCK][256];

    const int warp = threadIdx.x >> 5;
    const int lane = threadIdx.x & 31;
    const int t = blockIdx.x * WARPS_PER_BLOCK + warp;
    if (t >= T) return;

    // ---- load 8 logits per lane (lane l owns experts [8l, 8l+8), all in group l>>2)
    const float* lg = logits + (size_t)t * 256 + lane * 8;
    float4 x0 = *(const float4*)(lg);
    float4 x1 = *(const float4*)(lg + 4);
    float x[8] = {x0.x, x0.y, x0.z, x0.w, x1.x, x1.y, x1.z, x1.w};

    const float4* bp = (const float4*)(bias + lane * 8);
    float4 b0 = __ldg(bp);
    float4 b1 = __ldg(bp + 1);
    float bv[8] = {b0.x, b0.y, b0.z, b0.w, b1.x, b1.y, b1.z, b1.w};

    // ---- sigmoid + bias; stage unbiased scores in smem for the final gather
    float sb[8];
    #pragma unroll
    for (int i = 0; i < 8; i++) {
        float si = 1.0f / (1.0f + expf(-x[i]));
        sb[i] = si + bv[i];
        s_scores[warp][lane * 8 + i] = si;
    }

    // ---- group top-2 sum: per-lane top2 of 8, merge across the 4 lanes of the group
    const float NEG_INF = __int_as_float(0xff800000);
    float m1 = NEG_INF, m2 = NEG_INF;
    #pragma unroll
    for (int i = 0; i < 8; i++) {
        float v = sb[i];
        if (v > m1) { m2 = m1; m1 = v; }
        else if (v > m2) { m2 = v; }
    }
    #pragma unroll
    for (int off = 1; off <= 2; off <<= 1) {
        float o1 = __shfl_xor_sync(FULL, m1, off);
        float o2 = __shfl_xor_sync(FULL, m2, off);
        float n1 = fmaxf(m1, o1);
        float n2 = fmaxf(fminf(m1, o1), fmaxf(m2, o2));
        m1 = n1; m2 = n2;
    }
    float gscore = m1 + m2;   // identical across the 4 lanes of each group

    // ---- broadcast all 8 group scores; every lane computes the same top-4 mask
    float g[8];
    #pragma unroll
    for (int gi = 0; gi < 8; gi++) g[gi] = __shfl_sync(FULL, gscore, gi * 4);

    unsigned gmask = 0;
    #pragma unroll
    for (int k = 0; k < 4; k++) {
        float best = NEG_INF; int bi = 0;
        #pragma unroll
        for (int gi = 0; gi < 8; gi++) {
            bool take = !((gmask >> gi) & 1u) && (g[gi] > best);
            if (take) { best = g[gi]; bi = gi; }
        }
        gmask |= 1u << bi;
    }

    // ---- mask non-selected groups to 0.0 (reference semantics)
    bool sel = (gmask >> (lane >> 2)) & 1u;
    #pragma unroll
    for (int i = 0; i < 8; i++) sb[i] = sel ? sb[i] : 0.0f;

    // ---- 8 rounds of warp argmax (tie-break: lowest index, matching jax top_k)
    int myid = 0;
    #pragma unroll
    for (int k = 0; k < 8; k++) {
        float v = sb[0]; int vi = 0;
        #pragma unroll
        for (int i = 1; i < 8; i++) {
            if (sb[i] > v) { v = sb[i]; vi = i; }
        }
        int gidx = lane * 8 + vi;
        #pragma unroll
        for (int off = 16; off; off >>= 1) {
            float ov = __shfl_xor_sync(FULL, v, off);
            int   oi = __shfl_xor_sync(FULL, gidx, off);
            if (ov > v || (ov == v && oi < gidx)) { v = ov; gidx = oi; }
        }
        if (lane == k) myid = gidx;
        // knock out the winner with predicated (static-index) writes
        if ((gidx >> 3) == lane) {
            int li = gidx & 7;
            #pragma unroll
            for (int i = 0; i < 8; i++)
                if (i == li) sb[i] = NEG_INF;
        }
    }

    __syncwarp();

    // ---- gather unbiased weights, normalize, scale
    float w = 0.0f;
    if (lane < 8) w = s_scores[warp][myid];
    float sum = w;
    sum += __shfl_xor_sync(FULL, sum, 1);
    sum += __shfl_xor_sync(FULL, sum, 2);
    sum += __shfl_xor_sync(FULL, sum, 4);
    float wn = w / sum * 2.5f;

    // ---- outputs: [ weights (T*8) | ids-as-f32 (T*8) | logits (T*256) ]
    if (lane < 8) {
        out[(size_t)t * 8 + lane] = wn;
        out[(size_t)T * 8 + (size_t)t * 8 + lane] = (float)myid;
    }
    float* lo = out + (size_t)T * 16 + (size_t)t * 256 + lane * 8;
    *(float4*)(lo)     = x0;
    *(float4*)(lo + 4) = x1;
}

extern "C" void kernel_launch(void* const* d_in, const int* in_sizes, int n_in,
                              void* d_out, int out_size)
{
    // inputs (metadata order): hidden_states [T,7168] (unused), router_logits [T,256],
    // correction_bias [256]
    const float* logits = (const float*)d_in[1];
    const float* bias   = (const float*)d_in[2];
    float* out = (float*)d_out;

    int T = in_sizes[1] / 256;
    int blocks = (T + WARPS_PER_BLOCK - 1) / WARPS_PER_BLOCK;
    topk_route_kernel<<<blocks, WARPS_PER_BLOCK * 32>>>(logits, bias, out, T);
}

// round 4
// speedup vs baseline: 1.9870x; 1.9870x over previous
#include <cuda_runtime.h>
#include <math.h>
#include <stdint.h>

#define FULL 0xFFFFFFFFu

// monotone float->u32 key: order(key) == order(float), all non-NaN
__device__ __forceinline__ unsigned f2key(float f) {
    unsigned b = __float_as_uint(f);
    return (b & 0x80000000u) ? ~b : (b | 0x80000000u);
}
__device__ __forceinline__ float key2f(unsigned k) {
    unsigned b = (k & 0x80000000u) ? (k ^ 0x80000000u) : ~k;
    return __uint_as_float(b);
}

#define CE(i, j) { unsigned a_ = s[i], b_ = s[j]; s[i] = umax(a_, b_); s[j] = umin(a_, b_); }

__global__ __launch_bounds__(128)
void topk_route_kernel(const float* __restrict__ logits,
                       const float* __restrict__ bias,
                       float* __restrict__ out, int T)
{
    const int lane = threadIdx.x & 31;
    const int warp = threadIdx.x >> 5;
    const int t = blockIdx.x * 4 + warp;
    if (t >= T) return;

    // lane l owns experts [8l, 8l+8); all 8 are in group l>>2
    const float* lg = logits + (size_t)t * 256 + lane * 8;
    float4 x0 = *(const float4*)lg;
    float4 x1 = *(const float4*)(lg + 4);

    // passthrough logits immediately (frees x regs)
    float* lo = out + (size_t)T * 16 + (size_t)t * 256 + lane * 8;
    *(float4*)lo = x0;
    *(float4*)(lo + 4) = x1;

    const float4* bp = (const float4*)(bias + lane * 8);
    float4 b0 = __ldg(bp), b1 = __ldg(bp + 1);

    float xx[8] = {x0.x, x0.y, x0.z, x0.w, x1.x, x1.y, x1.z, x1.w};
    float bb[8] = {b0.x, b0.y, b0.z, b0.w, b1.x, b1.y, b1.z, b1.w};

    // sigmoid + bias -> monotone keys (orig order kept for index recovery)
    unsigned orig[8], s[8];
    #pragma unroll
    for (int i = 0; i < 8; i++) {
        float si = 1.0f / (1.0f + expf(-xx[i]));   // precise: ids must be exact
        float sb = si + bb[i];
        orig[i] = f2key(sb);
        s[i] = orig[i];
    }

    // ---- per-lane descending sort (Batcher odd-even, 19 comparators)
    CE(0,1) CE(2,3) CE(4,5) CE(6,7)
    CE(0,2) CE(1,3) CE(4,6) CE(5,7)
    CE(1,2) CE(5,6)
    CE(0,4) CE(1,5) CE(2,6) CE(3,7)
    CE(2,4) CE(3,5)
    CE(1,2) CE(3,4) CE(5,6)

    // ---- group score = top2 sum; per-lane top2 is free: s[0], s[1]
    unsigned m1 = s[0], m2 = s[1];
    #pragma unroll
    for (int off = 1; off <= 2; off <<= 1) {
        unsigned o1 = __shfl_xor_sync(FULL, m1, off);
        unsigned o2 = __shfl_xor_sync(FULL, m2, off);
        unsigned lo2 = umin(m1, o1);
        m1 = umax(m1, o1);
        m2 = umax(lo2, umax(m2, o2));
    }
    float gs = key2f(m1) + key2f(m2);   // identical across each quad

    // broadcast the 8 group scores; lane computes rank of its OWN group
    float g[8];
    #pragma unroll
    for (int j = 0; j < 8; j++) g[j] = __shfl_sync(FULL, gs, j * 4);
    int grp = lane >> 2;
    int rank = 0;
    #pragma unroll
    for (int j = 0; j < 8; j++)
        rank += ((g[j] > gs) || (g[j] == gs && j < grp)) ? 1 : 0;
    bool sel = rank < 4;   // top-4 groups, exact jax tie semantics

    // mask unselected groups to key(0.0f) — sorted order trivially preserved
    #pragma unroll
    for (int i = 0; i < 8; i++) s[i] = sel ? s[i] : 0x80000000u;

    // ---- 8 extraction rounds: redux-max of heads + winner-lane shift
    unsigned krec = 0; int wrec = 0;
    #pragma unroll
    for (int r = 0; r < 8; r++) {
        unsigned kmax = __reduce_max_sync(FULL, s[0]);
        unsigned bal = __ballot_sync(FULL, s[0] == kmax);
        int wl = __ffs((int)bal) - 1;       // lowest lane = lowest expert index
        if (lane == r) { krec = kmax; wrec = wl; }
        if (r < 7) {
            bool p = (lane == wl);
            #pragma unroll
            for (int i = 0; i < 7; i++) s[i] = p ? s[i + 1] : s[i];
        }
    }

    // ---- index recovery (warp-parallel): lane k finds pos of krec in lane wrec's orig[]
    unsigned gk[8];
    #pragma unroll
    for (int i = 0; i < 8; i++) gk[i] = __shfl_sync(FULL, orig[i], wrec);
    int pos = 7;
    #pragma unroll
    for (int i = 6; i >= 0; i--) pos = (gk[i] == krec) ? i : pos;  // first match
    int gidx = (wrec << 3) + pos;

    // ---- weight = unbiased score = biased − bias ; normalize; scale
    float w = key2f(krec) - __ldg(bias + gidx);
    float sum = w;
    sum += __shfl_xor_sync(FULL, sum, 1);
    sum += __shfl_xor_sync(FULL, sum, 2);
    sum += __shfl_xor_sync(FULL, sum, 4);
    float wn = w / sum * 2.5f;

    if (lane < 8) {
        out[(size_t)t * 8 + lane] = wn;
        out[(size_t)T * 8 + (size_t)t * 8 + lane] = (float)gidx;
    }
}

extern "C" void kernel_launch(void* const* d_in, const int* in_sizes, int n_in,
                              void* d_out, int out_size)
{
    // inputs: hidden_states (unused), router_logits [T,256], correction_bias [256]
    const float* logits = (const float*)d_in[1];
    const float* bias   = (const float*)d_in[2];
    float* out = (float*)d_out;

    int T = in_sizes[1] / 256;
    int blocks = (T + 3) / 4;
    topk_route_kernel<<<blocks, 128>>>(logits, bias, out, T);
}